// round 14
// baseline (speedup 1.0000x reference)
#include <cuda_runtime.h>
#include <cuda_fp16.h>
#include <cstdint>

// PatchEmbeddings: out[b,1+n,h] = (patchify(x)[b,n,:] @ W)[h] + bias[h] + pos[b,1+n,h]
//                  out[b,0,h]   = cls[b,0,h] + pos[b,0,h]
// GEMM M=32768, K=768, N=256; m16n8k16 f16. BM=128, BN=256, BK=96 (2 pixel rows).
// 512 threads, warp tile 32x64. B double-buffered (2x64KB) via cp.async with
// issue-after-barrier (full compute phase of slack); A double-buffered (2x32KB).
// K tiles are stored as two 48-k sub-tiles so all swizzle math matches BK=48.

#define ITERS 8
#define THREADS 512

__device__ __align__(16) uint8_t WT[16u * 1536u * 16u];  // 384 KB tiled fp16 W

__device__ __forceinline__ void mma_f16(float* c, const uint32_t* a, const uint32_t* b) {
    asm volatile(
        "mma.sync.aligned.m16n8k16.row.col.f32.f16.f16.f32 "
        "{%0,%1,%2,%3}, {%4,%5,%6,%7}, {%8,%9}, {%0,%1,%2,%3};"
        : "+f"(c[0]), "+f"(c[1]), "+f"(c[2]), "+f"(c[3])
        : "r"(a[0]), "r"(a[1]), "r"(a[2]), "r"(a[3]), "r"(b[0]), "r"(b[1]));
}

__device__ __forceinline__ void ldsm4(uint32_t& r0, uint32_t& r1, uint32_t& r2,
                                      uint32_t& r3, uint32_t addr) {
    asm volatile("ldmatrix.sync.aligned.m8n8.x4.shared.b16 {%0,%1,%2,%3}, [%4];"
                 : "=r"(r0), "=r"(r1), "=r"(r2), "=r"(r3) : "r"(addr));
}

__device__ __forceinline__ uint32_t pack2(float a, float b) {
    __half2 h = __floats2half2_rn(a, b);
    return *reinterpret_cast<uint32_t*>(&h);
}

#define CP_ASYNC16(dst, src) \
    asm volatile("cp.async.cg.shared.global [%0], [%1], 16;" :: "r"(dst), "l"(src) : "memory")
#define CP_COMMIT() asm volatile("cp.async.commit_group;" ::: "memory")
#define CP_WAIT0()  asm volatile("cp.async.wait_group 0;" ::: "memory")

// ---------------- prekernel: W -> fp16, transposed + tile-ordered ----------------
// chunk lg = blk*1536 + l (blk = 48-k block 0..15); n = l/6, c = l%6;
// halves = W[blk*48 + c*8 .. +8][n]
__global__ void prep_w(const float* __restrict__ W) {
    const int lg = blockIdx.x * 256 + threadIdx.x;   // 0..24575
    const int it = lg / 1536;
    const int l  = lg % 1536;
    const int n  = l / 6, c = l % 6;
    const float* src = W + (it * 48 + c * 8) * 256 + n;
    uint4 u;
    u.x = pack2(src[0 * 256], src[1 * 256]);
    u.y = pack2(src[2 * 256], src[3 * 256]);
    u.z = pack2(src[4 * 256], src[5 * 256]);
    u.w = pack2(src[6 * 256], src[7 * 256]);
    *(uint4*)(WT + (size_t)lg * 16) = u;
}

// ---------------- main kernel ----------------
// smem: A[buf] @ buf*32768 (+sub*16384); B @ 65536 + stg*65536 (+sub*32768)
__global__ __launch_bounds__(THREADS, 1)
void patch_gemm(const float* __restrict__ x,
                const float* __restrict__ bias,
                const float* __restrict__ cls,
                const float* __restrict__ pos,
                float* __restrict__ out)
{
    extern __shared__ __align__(128) uint8_t smem[];

    const int tid    = threadIdx.x;
    const int lane   = tid & 31;
    const int warp   = tid >> 5;
    const int warp_m = warp & 3;    // 4 x 32 m-rows
    const int warp_n = warp >> 2;   // 4 x 64 n-cols
    const int bm     = blockIdx.x;  // 0..255

    const uint32_t sbase = (uint32_t)__cvta_generic_to_shared(smem);

    // ---- fold cls row ----
    if (bm < 32 && tid < 256) {
        int o = bm * 1025 * 256 + tid;
        out[o] = cls[bm * 256 + tid] + pos[o];
    }

    // ---- A loader geometry (per 48-k sub-tile: 1536 float4, 3/thread) ----
    const int bb = bm >> 3;
    int a_src[3];
    uint32_t a_dst[3];
    #pragma unroll
    for (int j = 0; j < 3; j++) {
        const int l   = tid + THREADS * j;
        const int seg = l / 384;
        const int f   = l % 384;
        const int prg = (bm & 7) * 4 + seg;
        a_src[j] = (bb * 512 + prg * 16) * 1536 + f * 4;
        const int jp = f / 12, f4 = f % 12;
        const int m  = seg * 32 + jp;
        const int c  = f4 >> 1, h = f4 & 1;
        a_dst[j] = (uint32_t)(m * 128 + ((c ^ (m & 7)) << 4) + h * 8);
    }

    // ---- B loader geometry (per sub-tile: 1536 chunks, 3/thread) ----
    uint32_t b_dst[3];
    #pragma unroll
    for (int j = 0; j < 3; j++) {
        const int l = tid + THREADS * j;
        const int n = l / 6, c = l % 6;
        b_dst[j] = (uint32_t)(n * 128 + ((c ^ (n & 7)) << 4));
    }

    // ---- ldmatrix bases ----
    const int rowA = warp_m * 32 + (lane & 15);
    const uint32_t aBase = sbase + (uint32_t)(rowA * 128);
    const int xrA = rowA & 7;
    const int hiA = lane >> 4;
    const int rowB = warp_n * 64 + ((lane >> 4) << 3) + (lane & 7);
    const uint32_t bBase = sbase + 65536u + (uint32_t)(rowB * 128);
    const int xrB = rowB & 7;           // invariant across nj (stride 16)
    const int hiB = (lane >> 3) & 1;

    float acc[2][8][4];
    #pragma unroll
    for (int i = 0; i < 2; i++)
        #pragma unroll
        for (int j = 0; j < 8; j++)
            #pragma unroll
            for (int k = 0; k < 4; k++) acc[i][j][k] = 0.f;

    // ---- prologue: B blocks 0,1 -> stage 0; A iter 0 -> buf 0 ----
    {
        #pragma unroll
        for (int s = 0; s < 2; s++) {
            const uint8_t* ws = WT + (size_t)s * 1536 * 16;
            const uint32_t bd = sbase + 65536u + (uint32_t)(s * 32768);
            #pragma unroll
            for (int j = 0; j < 3; j++)
                CP_ASYNC16(bd + b_dst[j], ws + (tid + THREADS * j) * 16);
        }
        CP_COMMIT();
        #pragma unroll
        for (int s = 0; s < 2; s++)
            #pragma unroll
            for (int j = 0; j < 3; j++) {
                float4 v = *(const float4*)(x + a_src[j] + s * 1536);
                uint2 u; u.x = pack2(v.x, v.y); u.y = pack2(v.z, v.w);
                *(uint2*)(smem + s * 16384 + a_dst[j]) = u;
            }
    }

    int bufA = 0, stgB = 0;
    #pragma unroll 2
    for (int it = 0; it < ITERS; it++) {
        const int pf = (it + 1 < ITERS);

        CP_WAIT0();       // G_it (committed a full iteration ago)
        __syncthreads();  // B wait uniform + A STS of prev iter visible

        // ---- issue next B group + next A LDGs (safe: all warps past barrier) ----
        float4 va[6];
        if (pf) {
            #pragma unroll
            for (int s = 0; s < 2; s++) {
                const uint8_t* ws = WT + (size_t)(2 * (it + 1) + s) * 1536 * 16;
                const uint32_t bd = sbase + 65536u
                                  + (uint32_t)((stgB ^ 1) * 65536 + s * 32768);
                #pragma unroll
                for (int j = 0; j < 3; j++)
                    CP_ASYNC16(bd + b_dst[j], ws + (tid + THREADS * j) * 16);
            }
            CP_COMMIT();
            const float* xa = x + (it + 1) * 3072;
            #pragma unroll
            for (int s = 0; s < 2; s++)
                #pragma unroll
                for (int j = 0; j < 3; j++)
                    va[s * 3 + j] = *(const float4*)(xa + a_src[j] + s * 1536);
        }

        // ---- compute: 6 ksteps x (6 LDSM.x4 + 16 HMMA) ----
        const uint32_t ab  = aBase + (uint32_t)(bufA * 32768);
        const uint32_t bbf = bBase + (uint32_t)(stgB * 65536);
        #pragma unroll
        for (int ks = 0; ks < 6; ks++) {
            const int sub = ks / 3, ksl = ks % 3;
            uint32_t af[2][4], bf[8][2];
            const uint32_t ca = (uint32_t)(((2 * ksl + hiA) ^ xrA) << 4)
                              + (uint32_t)(sub * 16384);
            const uint32_t cb = (uint32_t)(((2 * ksl + hiB) ^ xrB) << 4)
                              + (uint32_t)(sub * 32768);
            #pragma unroll
            for (int mi = 0; mi < 2; mi++)
                ldsm4(af[mi][0], af[mi][1], af[mi][2], af[mi][3],
                      ab + (uint32_t)(mi * 2048) + ca);
            #pragma unroll
            for (int nj = 0; nj < 4; nj++)
                ldsm4(bf[2 * nj][0], bf[2 * nj][1], bf[2 * nj + 1][0], bf[2 * nj + 1][1],
                      bbf + (uint32_t)(nj * 2048) + cb);
            #pragma unroll
            for (int mi = 0; mi < 2; mi++)
                #pragma unroll
                for (int ni = 0; ni < 8; ni++)
                    mma_f16(acc[mi][ni], af[mi], bf[ni]);
        }

        // ---- stage next A tile (visibility via next iter's barrier) ----
        if (pf) {
            uint8_t* ad = smem + (bufA ^ 1) * 32768;
            #pragma unroll
            for (int s = 0; s < 2; s++)
                #pragma unroll
                for (int j = 0; j < 3; j++) {
                    float4 v = va[s * 3 + j];
                    uint2 u; u.x = pack2(v.x, v.y); u.y = pack2(v.z, v.w);
                    *(uint2*)(ad + s * 16384 + a_dst[j]) = u;
                }
            bufA ^= 1;
            stgB ^= 1;
        }
    }

    // ---- epilogue: + bias + pos, rows shifted +1 for cls ----
    const int grp = lane >> 2;
    const int tg  = lane & 3;
    const int gn0 = warp_n * 64;

    float2 bv[8];
    #pragma unroll
    for (int ni = 0; ni < 8; ni++)
        bv[ni] = *(const float2*)(bias + gn0 + ni * 8 + 2 * tg);

    #pragma unroll
    for (int mi = 0; mi < 2; mi++) {
        const int gm0 = bm * 128 + warp_m * 32 + mi * 16 + grp;
        #pragma unroll
        for (int half = 0; half < 2; half++) {
            const int r     = gm0 + half * 8;
            const int bt    = r >> 10;
            const int tok   = r & 1023;
            const int obase = (bt * 1025 + 1 + tok) * 256;
            #pragma unroll
            for (int ni = 0; ni < 8; ni++) {
                const int n = gn0 + ni * 8 + 2 * tg;
                float2 pv = *(const float2*)(pos + obase + n);
                float2 o;
                o.x = acc[mi][ni][half * 2 + 0] + bv[ni].x + pv.x;
                o.y = acc[mi][ni][half * 2 + 1] + bv[ni].y + pv.y;
                *(float2*)(out + obase + n) = o;
            }
        }
    }
}

extern "C" void kernel_launch(void* const* d_in, const int* in_sizes, int n_in,
                              void* d_out, int out_size)
{
    const float* x    = (const float*)d_in[0];
    const float* W    = (const float*)d_in[1];
    const float* bias = (const float*)d_in[2];
    const float* cls  = (const float*)d_in[3];
    const float* pos  = (const float*)d_in[4];
    float* out = (float*)d_out;

    prep_w<<<96, 256>>>(W);

    cudaFuncSetAttribute(patch_gemm, cudaFuncAttributeMaxDynamicSharedMemorySize, 196608);
    patch_gemm<<<256, THREADS, 196608>>>(x, bias, cls, pos, out);
}

// round 15
// speedup vs baseline: 1.1829x; 1.1829x over previous
#include <cuda_runtime.h>
#include <cuda_fp16.h>
#include <cstdint>

// PatchEmbeddings: out[b,1+n,h] = (patchify(x)[b,n,:] @ W)[h] + bias[h] + pos[b,1+n,h]
//                  out[b,0,h]   = cls[b,0,h] + pos[b,0,h]
// GEMM M=32768, K=768, N=256; m16n8k16 f16. BM=128, BN=256, BK=48.
// 512 threads, warp tile 32x64. B triple-buffered cp.async (wait_group<1>),
// A double-buffered. B fragments loaded in two 4-frag halves per kstep to cut
// live registers and give ptxas cross-kstep scheduling slack (RF was exact-full).

#define ITERS 16
#define THREADS 512

__device__ __align__(16) uint8_t WT[16u * 1536u * 16u];  // 384 KB tiled fp16 W

__device__ __forceinline__ void mma_f16(float* c, const uint32_t* a, const uint32_t* b) {
    asm volatile(
        "mma.sync.aligned.m16n8k16.row.col.f32.f16.f16.f32 "
        "{%0,%1,%2,%3}, {%4,%5,%6,%7}, {%8,%9}, {%0,%1,%2,%3};"
        : "+f"(c[0]), "+f"(c[1]), "+f"(c[2]), "+f"(c[3])
        : "r"(a[0]), "r"(a[1]), "r"(a[2]), "r"(a[3]), "r"(b[0]), "r"(b[1]));
}

__device__ __forceinline__ void ldsm4(uint32_t& r0, uint32_t& r1, uint32_t& r2,
                                      uint32_t& r3, uint32_t addr) {
    asm volatile("ldmatrix.sync.aligned.m8n8.x4.shared.b16 {%0,%1,%2,%3}, [%4];"
                 : "=r"(r0), "=r"(r1), "=r"(r2), "=r"(r3) : "r"(addr));
}

__device__ __forceinline__ uint32_t pack2(float a, float b) {
    __half2 h = __floats2half2_rn(a, b);
    return *reinterpret_cast<uint32_t*>(&h);
}

#define CP_ASYNC16(dst, src) \
    asm volatile("cp.async.cg.shared.global [%0], [%1], 16;" :: "r"(dst), "l"(src) : "memory")
#define CP_COMMIT() asm volatile("cp.async.commit_group;" ::: "memory")
#define CP_WAIT0()  asm volatile("cp.async.wait_group 0;" ::: "memory")
#define CP_WAIT1()  asm volatile("cp.async.wait_group 1;" ::: "memory")

// ---------------- prekernel: W -> fp16, transposed + tile-ordered ----------------
// thread -> (it, c, n) with consecutive lanes on consecutive n: every one of the
// 8 W loads is a single 128B line per warp (fully coalesced).
// WT chunk index = it*1536 + n*6 + c ; halves = W[it*48 + c*8 .. +8][n]
__global__ void prep_w(const float* __restrict__ W) {
    const int gid = blockIdx.x * 256 + threadIdx.x;  // 0..24575
    const int it  = gid / 1536;
    const int r   = gid % 1536;
    const int c   = r >> 8;          // 0..5
    const int n   = r & 255;         // consecutive per lane
    const float* src = W + (it * 48 + c * 8) * 256 + n;
    uint4 u;
    u.x = pack2(src[0 * 256], src[1 * 256]);
    u.y = pack2(src[2 * 256], src[3 * 256]);
    u.z = pack2(src[4 * 256], src[5 * 256]);
    u.w = pack2(src[6 * 256], src[7 * 256]);
    *(uint4*)(WT + ((size_t)it * 1536 + n * 6 + c) * 16) = u;
}

// ---------------- main kernel ----------------
// smem: A[2] @ bufA*16384 (128 rows x 128B); B[3] @ 32768 + stage*32768
__global__ __launch_bounds__(THREADS, 1)
void patch_gemm(const float* __restrict__ x,
                const float* __restrict__ bias,
                const float* __restrict__ cls,
                const float* __restrict__ pos,
                float* __restrict__ out)
{
    extern __shared__ __align__(128) uint8_t smem[];

    const int tid    = threadIdx.x;
    const int lane   = tid & 31;
    const int warp   = tid >> 5;
    const int warp_m = warp & 3;    // 4 x 32 m-rows
    const int warp_n = warp >> 2;   // 4 x 64 n-cols
    const int bm     = blockIdx.x;  // 0..255

    const uint32_t sbase = (uint32_t)__cvta_generic_to_shared(smem);

    // ---- fold cls row ----
    if (bm < 32 && tid < 256) {
        int o = bm * 1025 * 256 + tid;
        out[o] = cls[bm * 256 + tid] + pos[o];
    }

    // ---- A loader: 1536 float4/iter, 3 per thread ----
    const int bb = bm >> 3;
    int a_src[3];
    uint32_t a_dst[3];
    #pragma unroll
    for (int j = 0; j < 3; j++) {
        const int l   = tid + THREADS * j;
        const int seg = l / 384;
        const int f   = l % 384;
        const int prg = (bm & 7) * 4 + seg;
        a_src[j] = (bb * 512 + prg * 16) * 1536 + f * 4;
        const int jp = f / 12, f4 = f % 12;
        const int m  = seg * 32 + jp;
        const int c  = f4 >> 1, h = f4 & 1;
        a_dst[j] = (uint32_t)(m * 128 + ((c ^ (m & 7)) << 4) + h * 8);
    }

    // ---- B loader: 1536 cp.async chunks/iter, 3 per thread (within-stage offs) ----
    uint32_t b_dst[3];
    #pragma unroll
    for (int j = 0; j < 3; j++) {
        const int l = tid + THREADS * j;
        const int n = l / 6, c = l % 6;
        b_dst[j] = (uint32_t)(n * 128 + ((c ^ (n & 7)) << 4));
    }

    // ---- ldmatrix bases ----
    const int rowA = warp_m * 32 + (lane & 15);
    const uint32_t aBase = sbase + (uint32_t)(rowA * 128);
    const int xrA = rowA & 7;
    const int hiA = lane >> 4;
    const int rowB = warp_n * 64 + ((lane >> 4) << 3) + (lane & 7);
    const uint32_t bBase = sbase + 32768u + (uint32_t)(rowB * 128);
    const int xrB = rowB & 7;           // invariant across nj (stride 16)
    const int hiB = (lane >> 3) & 1;

    float acc[2][8][4];
    #pragma unroll
    for (int i = 0; i < 2; i++)
        #pragma unroll
        for (int j = 0; j < 8; j++)
            #pragma unroll
            for (int k = 0; k < 4; k++) acc[i][j][k] = 0.f;

    // ---- prologue: B stage 0 (G0) + A iter 0 -> A buf 0 ----
    {
        const uint32_t bd = sbase + 32768u;   // stage 0
        #pragma unroll
        for (int j = 0; j < 3; j++)
            CP_ASYNC16(bd + b_dst[j], WT + (tid + THREADS * j) * 16);
        CP_COMMIT();
        #pragma unroll
        for (int j = 0; j < 3; j++) {
            float4 v = *(const float4*)(x + a_src[j]);
            uint2 u; u.x = pack2(v.x, v.y); u.y = pack2(v.z, v.w);
            *(uint2*)(smem + a_dst[j]) = u;
        }
    }

    int bufA = 0, stgB = 0;
    for (int it = 0; it < ITERS; it++) {
        const int pf = (it + 1 < ITERS);
        const int stgN = (stgB == 2) ? 0 : stgB + 1;
        float4 va[3];

        // issue next B group + next A LDGs
        if (pf) {
            const uint8_t* ws = WT + (size_t)(it + 1) * 1536 * 16;
            const uint32_t bd = sbase + 32768u + (uint32_t)(stgN * 32768);
            #pragma unroll
            for (int j = 0; j < 3; j++)
                CP_ASYNC16(bd + b_dst[j], ws + (tid + THREADS * j) * 16);
            CP_COMMIT();
            const float* xa = x + (it + 1) * 1536;
            #pragma unroll
            for (int j = 0; j < 3; j++)
                va[j] = *(const float4*)(xa + a_src[j]);
            CP_WAIT1();   // completes the group for THIS iter's stage (1 iter old)
        } else {
            CP_WAIT0();
        }
        __syncthreads();

        // ---- compute: 3 ksteps x (2 A-LDSM + 2x(2 B-LDSM + 8 HMMA)) ----
        const uint32_t ab  = aBase + (uint32_t)(bufA * 16384);
        const uint32_t bbf = bBase + (uint32_t)(stgB * 32768);
        #pragma unroll
        for (int ks = 0; ks < 3; ks++) {
            uint32_t af[2][4];
            const uint32_t ca = (uint32_t)(((2 * ks + hiA) ^ xrA) << 4);
            const uint32_t cb = (uint32_t)(((2 * ks + hiB) ^ xrB) << 4);
            #pragma unroll
            for (int mi = 0; mi < 2; mi++)
                ldsm4(af[mi][0], af[mi][1], af[mi][2], af[mi][3],
                      ab + (uint32_t)(mi * 2048) + ca);
            #pragma unroll
            for (int h = 0; h < 2; h++) {        // two 4-frag n halves
                uint32_t bf[4][2];
                ldsm4(bf[0][0], bf[0][1], bf[1][0], bf[1][1],
                      bbf + (uint32_t)((h * 2 + 0) * 2048) + cb);
                ldsm4(bf[2][0], bf[2][1], bf[3][0], bf[3][1],
                      bbf + (uint32_t)((h * 2 + 1) * 2048) + cb);
                #pragma unroll
                for (int mi = 0; mi < 2; mi++)
                    #pragma unroll
                    for (int nj = 0; nj < 4; nj++)
                        mma_f16(acc[mi][h * 4 + nj], af[mi], bf[nj]);
            }
        }

        // ---- stage next A tile (visibility via next iter's barrier) ----
        if (pf) {
            uint8_t* ad = smem + (bufA ^ 1) * 16384;
            #pragma unroll
            for (int j = 0; j < 3; j++) {
                uint2 u; u.x = pack2(va[j].x, va[j].y); u.y = pack2(va[j].z, va[j].w);
                *(uint2*)(ad + a_dst[j]) = u;
            }
            bufA ^= 1;
            stgB = stgN;
        }
    }

    // ---- epilogue: + bias + pos, rows shifted +1 for cls ----
    const int grp = lane >> 2;
    const int tg  = lane & 3;
    const int gn0 = warp_n * 64;

    float2 bv[8];
    #pragma unroll
    for (int ni = 0; ni < 8; ni++)
        bv[ni] = *(const float2*)(bias + gn0 + ni * 8 + 2 * tg);

    #pragma unroll
    for (int mi = 0; mi < 2; mi++) {
        const int gm0 = bm * 128 + warp_m * 32 + mi * 16 + grp;
        #pragma unroll
        for (int half = 0; half < 2; half++) {
            const int r     = gm0 + half * 8;
            const int bt    = r >> 10;
            const int tok   = r & 1023;
            const int obase = (bt * 1025 + 1 + tok) * 256;
            #pragma unroll
            for (int ni = 0; ni < 8; ni++) {
                const int n = gn0 + ni * 8 + 2 * tg;
                float2 pv = *(const float2*)(pos + obase + n);
                float2 o;
                o.x = acc[mi][ni][half * 2 + 0] + bv[ni].x + pv.x;
                o.y = acc[mi][ni][half * 2 + 1] + bv[ni].y + pv.y;
                *(float2*)(out + obase + n) = o;
            }
        }
    }
}

extern "C" void kernel_launch(void* const* d_in, const int* in_sizes, int n_in,
                              void* d_out, int out_size)
{
    const float* x    = (const float*)d_in[0];
    const float* W    = (const float*)d_in[1];
    const float* bias = (const float*)d_in[2];
    const float* cls  = (const float*)d_in[3];
    const float* pos  = (const float*)d_in[4];
    float* out = (float*)d_out;

    prep_w<<<96, 256>>>(W);

    cudaFuncSetAttribute(patch_gemm, cudaFuncAttributeMaxDynamicSharedMemorySize, 131072);
    patch_gemm<<<256, THREADS, 131072>>>(x, bias, cls, pos, out);
}

// round 16
// speedup vs baseline: 1.1836x; 1.0006x over previous
#include <cuda_runtime.h>
#include <cuda_fp16.h>
#include <cstdint>

// PatchEmbeddings: out[b,1+n,h] = (patchify(x)[b,n,:] @ W)[h] + bias[h] + pos[b,1+n,h]
//                  out[b,0,h]   = cls[b,0,h] + pos[b,0,h]
// GEMM M=32768, K=768, N=256; m16n8k16 f16. BM=128, BN=256, BK=48.
// 512 threads, warp tile 32x64. B triple-buffered cp.async (wait_group<1>),
// A double-buffered. mma asm non-volatile (data-dep ordered); ldsm ordered by
// "memory" clobber only. prep_w fully coalesced.

#define ITERS 16
#define THREADS 512

__device__ __align__(16) uint8_t WT[16u * 1536u * 16u];  // 384 KB tiled fp16 W

__device__ __forceinline__ void mma_f16(float* c, const uint32_t* a, const uint32_t* b) {
    asm("mma.sync.aligned.m16n8k16.row.col.f32.f16.f16.f32 "
        "{%0,%1,%2,%3}, {%4,%5,%6,%7}, {%8,%9}, {%0,%1,%2,%3};"
        : "+f"(c[0]), "+f"(c[1]), "+f"(c[2]), "+f"(c[3])
        : "r"(a[0]), "r"(a[1]), "r"(a[2]), "r"(a[3]), "r"(b[0]), "r"(b[1]));
}

__device__ __forceinline__ void ldsm4(uint32_t& r0, uint32_t& r1, uint32_t& r2,
                                      uint32_t& r3, uint32_t addr) {
    asm("ldmatrix.sync.aligned.m8n8.x4.shared.b16 {%0,%1,%2,%3}, [%4];"
        : "=r"(r0), "=r"(r1), "=r"(r2), "=r"(r3) : "r"(addr) : "memory");
}

__device__ __forceinline__ uint32_t pack2(float a, float b) {
    __half2 h = __floats2half2_rn(a, b);
    return *reinterpret_cast<uint32_t*>(&h);
}

#define CP_ASYNC16(dst, src) \
    asm volatile("cp.async.cg.shared.global [%0], [%1], 16;" :: "r"(dst), "l"(src) : "memory")
#define CP_COMMIT() asm volatile("cp.async.commit_group;" ::: "memory")
#define CP_WAIT0()  asm volatile("cp.async.wait_group 0;" ::: "memory")
#define CP_WAIT1()  asm volatile("cp.async.wait_group 1;" ::: "memory")

// ---------------- prekernel: W -> fp16, transposed + tile-ordered ----------------
// thread -> (it, c, n), consecutive lanes on consecutive n: all 8 W loads are
// one 128B line per warp. WT chunk = it*1536 + n*6 + c = W[it*48+c*8 .. +8][n]
__global__ void prep_w(const float* __restrict__ W) {
    const int gid = blockIdx.x * 256 + threadIdx.x;  // 0..24575
    const int it  = gid / 1536;
    const int r   = gid % 1536;
    const int c   = r >> 8;          // 0..5
    const int n   = r & 255;
    const float* src = W + (it * 48 + c * 8) * 256 + n;
    uint4 u;
    u.x = pack2(src[0 * 256], src[1 * 256]);
    u.y = pack2(src[2 * 256], src[3 * 256]);
    u.z = pack2(src[4 * 256], src[5 * 256]);
    u.w = pack2(src[6 * 256], src[7 * 256]);
    *(uint4*)(WT + ((size_t)it * 1536 + n * 6 + c) * 16) = u;
}

// ---------------- main kernel ----------------
// smem: A[2] @ bufA*16384 (128 rows x 128B); B[3] @ 32768 + stage*32768
__global__ __launch_bounds__(THREADS, 1)
void patch_gemm(const float* __restrict__ x,
                const float* __restrict__ bias,
                const float* __restrict__ cls,
                const float* __restrict__ pos,
                float* __restrict__ out)
{
    extern __shared__ __align__(128) uint8_t smem[];

    const int tid    = threadIdx.x;
    const int lane   = tid & 31;
    const int warp   = tid >> 5;
    const int warp_m = warp & 3;    // 4 x 32 m-rows
    const int warp_n = warp >> 2;   // 4 x 64 n-cols
    const int bm     = blockIdx.x;  // 0..255

    const uint32_t sbase = (uint32_t)__cvta_generic_to_shared(smem);

    // ---- fold cls row ----
    if (bm < 32 && tid < 256) {
        int o = bm * 1025 * 256 + tid;
        out[o] = cls[bm * 256 + tid] + pos[o];
    }

    // ---- A loader: 1536 float4/iter, 3 per thread ----
    const int bb = bm >> 3;
    int a_src[3];
    uint32_t a_dst[3];
    #pragma unroll
    for (int j = 0; j < 3; j++) {
        const int l   = tid + THREADS * j;
        const int seg = l / 384;
        const int f   = l % 384;
        const int prg = (bm & 7) * 4 + seg;
        a_src[j] = (bb * 512 + prg * 16) * 1536 + f * 4;
        const int jp = f / 12, f4 = f % 12;
        const int m  = seg * 32 + jp;
        const int c  = f4 >> 1, h = f4 & 1;
        a_dst[j] = (uint32_t)(m * 128 + ((c ^ (m & 7)) << 4) + h * 8);
    }

    // ---- B loader: 1536 cp.async chunks/iter, 3 per thread (within-stage offs) ----
    uint32_t b_dst[3];
    #pragma unroll
    for (int j = 0; j < 3; j++) {
        const int l = tid + THREADS * j;
        const int n = l / 6, c = l % 6;
        b_dst[j] = (uint32_t)(n * 128 + ((c ^ (n & 7)) << 4));
    }

    // ---- ldmatrix bases ----
    const int rowA = warp_m * 32 + (lane & 15);
    const uint32_t aBase = sbase + (uint32_t)(rowA * 128);
    const int xrA = rowA & 7;
    const int hiA = lane >> 4;
    const int rowB = warp_n * 64 + ((lane >> 4) << 3) + (lane & 7);
    const uint32_t bBase = sbase + 32768u + (uint32_t)(rowB * 128);
    const int xrB = rowB & 7;           // invariant across nj (stride 16)
    const int hiB = (lane >> 3) & 1;

    float acc[2][8][4];
    #pragma unroll
    for (int i = 0; i < 2; i++)
        #pragma unroll
        for (int j = 0; j < 8; j++)
            #pragma unroll
            for (int k = 0; k < 4; k++) acc[i][j][k] = 0.f;

    // ---- prologue: B stage 0 (G0) + A iter 0 -> A buf 0 ----
    {
        const uint32_t bd = sbase + 32768u;   // stage 0
        #pragma unroll
        for (int j = 0; j < 3; j++)
            CP_ASYNC16(bd + b_dst[j], WT + (tid + THREADS * j) * 16);
        CP_COMMIT();
        #pragma unroll
        for (int j = 0; j < 3; j++) {
            float4 v = *(const float4*)(x + a_src[j]);
            uint2 u; u.x = pack2(v.x, v.y); u.y = pack2(v.z, v.w);
            *(uint2*)(smem + a_dst[j]) = u;
        }
    }

    int bufA = 0, stgB = 0;
    for (int it = 0; it < ITERS; it++) {
        const int pf = (it + 1 < ITERS);
        const int stgN = (stgB == 2) ? 0 : stgB + 1;
        float4 va[3];

        // issue next B group + next A LDGs
        if (pf) {
            const uint8_t* ws = WT + (size_t)(it + 1) * 1536 * 16;
            const uint32_t bd = sbase + 32768u + (uint32_t)(stgN * 32768);
            #pragma unroll
            for (int j = 0; j < 3; j++)
                CP_ASYNC16(bd + b_dst[j], ws + (tid + THREADS * j) * 16);
            CP_COMMIT();
            const float* xa = x + (it + 1) * 1536;
            #pragma unroll
            for (int j = 0; j < 3; j++)
                va[j] = *(const float4*)(xa + a_src[j]);
            CP_WAIT1();   // completes the group for THIS iter's stage (1 iter old)
        } else {
            CP_WAIT0();
        }
        __syncthreads();

        // ---- compute: 3 ksteps x (6 LDSM.x4 + 16 HMMA) ----
        const uint32_t ab  = aBase + (uint32_t)(bufA * 16384);
        const uint32_t bbf = bBase + (uint32_t)(stgB * 32768);
        #pragma unroll
        for (int ks = 0; ks < 3; ks++) {
            uint32_t af[2][4], bf[8][2];
            const uint32_t ca = (uint32_t)(((2 * ks + hiA) ^ xrA) << 4);
            const uint32_t cb = (uint32_t)(((2 * ks + hiB) ^ xrB) << 4);
            #pragma unroll
            for (int mi = 0; mi < 2; mi++)
                ldsm4(af[mi][0], af[mi][1], af[mi][2], af[mi][3],
                      ab + (uint32_t)(mi * 2048) + ca);
            #pragma unroll
            for (int nj = 0; nj < 4; nj++)
                ldsm4(bf[2 * nj][0], bf[2 * nj][1], bf[2 * nj + 1][0], bf[2 * nj + 1][1],
                      bbf + (uint32_t)(nj * 2048) + cb);
            #pragma unroll
            for (int mi = 0; mi < 2; mi++)
                #pragma unroll
                for (int ni = 0; ni < 8; ni++)
                    mma_f16(acc[mi][ni], af[mi], bf[ni]);
        }

        // ---- stage next A tile (visibility via next iter's barrier) ----
        if (pf) {
            uint8_t* ad = smem + (bufA ^ 1) * 16384;
            #pragma unroll
            for (int j = 0; j < 3; j++) {
                uint2 u; u.x = pack2(va[j].x, va[j].y); u.y = pack2(va[j].z, va[j].w);
                *(uint2*)(ad + a_dst[j]) = u;
            }
            bufA ^= 1;
            stgB = stgN;
        }
    }

    // ---- epilogue: + bias + pos, rows shifted +1 for cls ----
    const int grp = lane >> 2;
    const int tg  = lane & 3;
    const int gn0 = warp_n * 64;

    float2 bv[8];
    #pragma unroll
    for (int ni = 0; ni < 8; ni++)
        bv[ni] = *(const float2*)(bias + gn0 + ni * 8 + 2 * tg);

    #pragma unroll
    for (int mi = 0; mi < 2; mi++) {
        const int gm0 = bm * 128 + warp_m * 32 + mi * 16 + grp;
        #pragma unroll
        for (int half = 0; half < 2; half++) {
            const int r     = gm0 + half * 8;
            const int bt    = r >> 10;
            const int tok   = r & 1023;
            const int obase = (bt * 1025 + 1 + tok) * 256;
            #pragma unroll
            for (int ni = 0; ni < 8; ni++) {
                const int n = gn0 + ni * 8 + 2 * tg;
                float2 pv = *(const float2*)(pos + obase + n);
                float2 o;
                o.x = acc[mi][ni][half * 2 + 0] + bv[ni].x + pv.x;
                o.y = acc[mi][ni][half * 2 + 1] + bv[ni].y + pv.y;
                *(float2*)(out + obase + n) = o;
            }
        }
    }
}

extern "C" void kernel_launch(void* const* d_in, const int* in_sizes, int n_in,
                              void* d_out, int out_size)
{
    const float* x    = (const float*)d_in[0];
    const float* W    = (const float*)d_in[1];
    const float* bias = (const float*)d_in[2];
    const float* cls  = (const float*)d_in[3];
    const float* pos  = (const float*)d_in[4];
    float* out = (float*)d_out;

    prep_w<<<96, 256>>>(W);

    cudaFuncSetAttribute(patch_gemm, cudaFuncAttributeMaxDynamicSharedMemorySize, 131072);
    patch_gemm<<<256, THREADS, 131072>>>(x, bias, cls, pos, out);
}